// round 7
// baseline (speedup 1.0000x reference)
#include <cuda_runtime.h>
#include <math.h>

// Problem constants
#define T_DIM 4
#define C_DIM 64
#define H_DIM 128
#define W_DIM 128
#define HW    (H_DIM * W_DIM)        // 16384
#define NPOS  (T_DIM * HW)           // 65536
#define NJ    96                     // padded offset-conv output channels
#define NJR   81                     // real offset channels (3*27)

// -------- device scratch (no allocations allowed) --------
__device__ __align__(16) float g_xt[NPOS * C_DIM];        // x channels-last: [t][h][w][c]
__device__ __align__(16) float g_off[NPOS * NJR];         // offsets: [pos][81]
__device__ __align__(16) float g_WtB[27 * C_DIM * NJ];    // offset weights: [tap][c][j], j padded to 96
__device__ __align__(16) float g_W2t[27 * C_DIM * C_DIM]; // main weights: [tap][c][o]

// ============================================================
// Kernel A: transpose x (T,C,H,W) -> xt (T,H,W,C)
// ============================================================
__global__ void transpose_kernel(const float* __restrict__ x) {
    __shared__ float tile[32][33];
    int th = blockIdx.z;             // t*128 + h
    int t = th >> 7, h = th & 127;
    int c0 = blockIdx.y * 32;        // 0 or 32
    int w0 = blockIdx.x * 32;        // 0,32,64,96
    int tx = threadIdx.x, ty = threadIdx.y;
    // read coalesced along w
    tile[ty][tx] = x[(((size_t)t * C_DIM + (c0 + ty)) * H_DIM + h) * W_DIM + (w0 + tx)];
    __syncthreads();
    // write coalesced along c
    g_xt[(((size_t)th * W_DIM) + (w0 + ty)) * C_DIM + (c0 + tx)] = tile[tx][ty];
}

// ============================================================
// Kernel W: re-layout weights
//   offset_w (81,64,3,3,3) -> g_WtB[tap][c][j pad 96]
//   weight   (64,64,3,3,3) -> g_W2t[tap][c][o]
// ============================================================
__global__ void prep_weights(const float* __restrict__ ow, const float* __restrict__ wgt) {
    int i = blockIdx.x * blockDim.x + threadIdx.x;
    if (i < 27 * 64 * NJ) {
        int j   = i % NJ;
        int c   = (i / NJ) % 64;
        int tap = i / (NJ * 64);
        g_WtB[i] = (j < NJR) ? ow[((size_t)j * 64 + c) * 27 + tap] : 0.f;
    }
    if (i < 27 * 64 * 64) {
        int o   = i % 64;
        int c   = (i / 64) % 64;
        int tap = i / (64 * 64);
        g_W2t[i] = wgt[((size_t)o * 64 + c) * 27 + tap];
    }
}

// ============================================================
// Kernel B: offset conv (implicit GEMM)
//   block = one (t,h) row: 128 w positions x 96 j, K = 27 taps * 64 c
//   smem: xrow [130][65] (w'=-1..128, padded stride), ws [64][96]
// ============================================================
#define SMEM_B ((130 * 65 + 64 * NJ) * 4)

__global__ void __launch_bounds__(256) offset_conv_kernel(const float* __restrict__ offb) {
    extern __shared__ float sm[];
    float* xrow = sm;               // 130*65
    float* ws   = sm + 130 * 65;    // 64*96

    int th = blockIdx.x;
    int t = th >> 7, h = th & 127;
    int tid = threadIdx.x;
    int tj = tid & 15;     // j group: j0 = tj*6
    int tw = tid >> 4;     // w group: w0 = tw*8

    float acc[8][6];
#pragma unroll
    for (int i = 0; i < 8; i++)
#pragma unroll
        for (int j = 0; j < 6; j++) acc[i][j] = 0.f;

    for (int kt = 0; kt < 3; kt++) {
        int ts = t + kt - 1;
        if (ts < 0 || ts >= T_DIM) continue;          // uniform across block
        for (int kh = 0; kh < 3; kh++) {
            int hs = h + kh - 1;
            if (hs < 0 || hs >= H_DIM) continue;      // uniform across block
            __syncthreads();                          // xrow reuse barrier
            const float* src = g_xt + ((size_t)(ts * H_DIM + hs) * W_DIM) * C_DIM;
            for (int idx = tid; idx < 130 * 64; idx += 256) {
                int wp = idx >> 6, c = idx & 63;
                int wg = wp - 1;
                xrow[wp * 65 + c] = (wg >= 0 && wg < W_DIM) ? src[(size_t)wg * C_DIM + c] : 0.f;
            }
            for (int kw = 0; kw < 3; kw++) {
                int tap = kt * 9 + kh * 3 + kw;
                __syncthreads();                      // ws reuse + xrow ready
                const float* wsrc = g_WtB + (size_t)tap * (64 * NJ);
                for (int idx = tid; idx < 64 * NJ; idx += 256) ws[idx] = wsrc[idx];
                __syncthreads();

                const float* ab = xrow + (tw * 8 + kw) * 65;
#pragma unroll 4
                for (int c = 0; c < 64; c++) {
                    float a[8], b[6];
#pragma unroll
                    for (int i = 0; i < 8; i++) a[i] = ab[i * 65 + c];
#pragma unroll
                    for (int j = 0; j < 6; j++) b[j] = ws[c * NJ + tj * 6 + j];
#pragma unroll
                    for (int i = 0; i < 8; i++)
#pragma unroll
                        for (int j = 0; j < 6; j++)
                            acc[i][j] = fmaf(a[i], b[j], acc[i][j]);
                }
            }
        }
    }

    size_t rowbase = (size_t)th * W_DIM;
#pragma unroll
    for (int j = 0; j < 6; j++) {
        int jg = tj * 6 + j;
        if (jg >= NJR) continue;
        float bias = offb[jg];
#pragma unroll
        for (int i = 0; i < 8; i++) {
            int w = tw * 8 + i;
            g_off[(rowbase + w) * NJR + jg] = acc[i][j] + bias;
        }
    }
}

// ============================================================
// Kernel C: deformable sampling + weight contraction + residual
//   block = one (t,h) row: 128 w positions x 64 out channels
//   per tap: build sampled tile s[128][64] (trilinear, zero-fill OOB),
//   then GEMM-accumulate with 64x64 tap weight.
// ============================================================
#define SMEM_C ((128 * 68 + 64 * 64 + 3 * 128) * 4)

__global__ void __launch_bounds__(256) deform_kernel(const float* __restrict__ x,
                                                     const float* __restrict__ gamma,
                                                     float* __restrict__ out) {
    extern __shared__ float sm[];
    float* stile = sm;                      // [128][68]
    float* w2s   = sm + 128 * 68;           // [64][64]
    float* sdt   = w2s + 64 * 64;           // [128]
    float* sdh   = sdt + 128;
    float* sdw   = sdh + 128;

    int th = blockIdx.x;
    int t = th >> 7, h = th & 127;
    int tid = threadIdx.x;
    int to = tid & 15;      // o group: o0 = to*4
    int tw = tid >> 4;      // w group: w0 = tw*8

    int wsamp = tid >> 1;           // sampling: each thread = one w, half the channels
    int cf = (tid & 1) * 32;

    float acc[8][4];
#pragma unroll
    for (int i = 0; i < 8; i++)
#pragma unroll
        for (int j = 0; j < 4; j++) acc[i][j] = 0.f;

    size_t prow = (size_t)th * W_DIM;

    for (int k = 0; k < 27; k++) {
        int kt = k / 9, kh = (k / 3) % 3, kw = k % 3;
        __syncthreads();            // protect smem reuse from previous tap's GEMM
        if (tid < 128) {
            size_t pb = (prow + tid) * NJR;
            sdt[tid] = g_off[pb + k];
            sdh[tid] = g_off[pb + 27 + k];
            sdw[tid] = g_off[pb + 54 + k];
        }
        const float* wsrc = g_W2t + (size_t)k * 4096;
        for (int idx = tid; idx < 4096; idx += 256) w2s[idx] = wsrc[idx];
        __syncthreads();

        // ---- build sampled tile ----
        {
            float tc = (float)(t + kt - 1) + sdt[wsamp];
            float hc = (float)(h + kh - 1) + sdh[wsamp];
            float wc = (float)(wsamp + kw - 1) + sdw[wsamp];
            float t0f = floorf(tc), h0f = floorf(hc), w0f = floorf(wc);
            float lt = tc - t0f, lh = hc - h0f, lw = wc - w0f;
            int t0 = (int)t0f, h0 = (int)h0f, w0 = (int)w0f;
            float wts[2] = {1.f - lt, lt};
            float whs[2] = {1.f - lh, lh};
            float wws[2] = {1.f - lw, lw};

            const float* cp[8];
            float cw[8];
            int n = 0;
#pragma unroll
            for (int dt = 0; dt < 2; dt++)
#pragma unroll
                for (int dh = 0; dh < 2; dh++)
#pragma unroll
                    for (int dw = 0; dw < 2; dw++) {
                        int ti = t0 + dt, hi = h0 + dh, wi = w0 + dw;
                        bool valid = (unsigned)ti < T_DIM && (unsigned)hi < H_DIM &&
                                     (unsigned)wi < W_DIM;
                        cw[n] = valid ? wts[dt] * whs[dh] * wws[dw] : 0.f;
                        cp[n] = valid
                                    ? (g_xt + (((size_t)ti * H_DIM + hi) * W_DIM + wi) * C_DIM + cf)
                                    : (g_xt + cf);   // safe dummy, weight is 0
                        n++;
                    }

            float* sd = stile + wsamp * 68 + cf;
#pragma unroll
            for (int cc = 0; cc < 32; cc += 4) {
                float4 a = make_float4(0.f, 0.f, 0.f, 0.f);
#pragma unroll
                for (int q = 0; q < 8; q++) {
                    float4 v = *reinterpret_cast<const float4*>(cp[q] + cc);
                    a.x = fmaf(cw[q], v.x, a.x);
                    a.y = fmaf(cw[q], v.y, a.y);
                    a.z = fmaf(cw[q], v.z, a.z);
                    a.w = fmaf(cw[q], v.w, a.w);
                }
                *reinterpret_cast<float4*>(sd + cc) = a;
            }
        }
        __syncthreads();

        // ---- GEMM accumulate: acc[w][o] += s[w][c] * w2s[c][o] ----
        const float* ab = stile + tw * 8 * 68;
#pragma unroll 4
        for (int c = 0; c < 64; c++) {
            float4 b = *reinterpret_cast<const float4*>(w2s + c * 64 + to * 4);
            float a[8];
#pragma unroll
            for (int i = 0; i < 8; i++) a[i] = ab[i * 68 + c];
#pragma unroll
            for (int i = 0; i < 8; i++) {
                acc[i][0] = fmaf(a[i], b.x, acc[i][0]);
                acc[i][1] = fmaf(a[i], b.y, acc[i][1]);
                acc[i][2] = fmaf(a[i], b.z, acc[i][2]);
                acc[i][3] = fmaf(a[i], b.w, acc[i][3]);
            }
        }
    }

    // ---- epilogue: out = gamma * conv + x  (layout T,C,H,W) ----
    float g = gamma[0];
#pragma unroll
    for (int jo = 0; jo < 4; jo++) {
        int o = to * 4 + jo;
        size_t ob = (((size_t)t * C_DIM + o) * H_DIM + h) * W_DIM;
#pragma unroll
        for (int i = 0; i < 8; i++) {
            int w = tw * 8 + i;
            out[ob + w] = fmaf(g, acc[i][jo], x[ob + w]);
        }
    }
}

// ============================================================
// launch
// ============================================================
extern "C" void kernel_launch(void* const* d_in, const int* in_sizes, int n_in,
                              void* d_out, int out_size) {
    const float* x     = (const float*)d_in[0];
    const float* ow    = (const float*)d_in[1];
    const float* ob    = (const float*)d_in[2];
    const float* wgt   = (const float*)d_in[3];
    const float* gamma = (const float*)d_in[4];
    float* out = (float*)d_out;

    // Idempotent; first (non-captured) correctness call makes these stick.
    cudaFuncSetAttribute(offset_conv_kernel,
                         cudaFuncAttributeMaxDynamicSharedMemorySize, SMEM_B);
    cudaFuncSetAttribute(deform_kernel,
                         cudaFuncAttributeMaxDynamicSharedMemorySize, SMEM_C);

    dim3 tb(32, 32);
    dim3 tg(4, 2, T_DIM * H_DIM);
    transpose_kernel<<<tg, tb>>>(x);

    prep_weights<<<(27 * 64 * NJ + 255) / 256, 256>>>(ow, wgt);

    offset_conv_kernel<<<T_DIM * H_DIM, 256, SMEM_B>>>(ob);

    deform_kernel<<<T_DIM * H_DIM, 256, SMEM_C>>>(x, gamma, out);
}

// round 8
// speedup vs baseline: 1.0000x; 1.0000x over previous
#include <cuda_runtime.h>
#include <math.h>

// Problem constants
#define T_DIM 4
#define C_DIM 64
#define H_DIM 128
#define W_DIM 128
#define HW    (H_DIM * W_DIM)        // 16384
#define NPOS  (T_DIM * HW)           // 65536
#define NJ    96                     // padded offset-conv output channels
#define NJR   81                     // real offset channels (3*27)

// -------- device scratch (no allocations allowed) --------
__device__ __align__(16) float g_xt[NPOS * C_DIM];        // x channels-last: [t][h][w][c]
__device__ __align__(16) float g_off[NPOS * NJR];         // offsets: [pos][81]
__device__ __align__(16) float g_WtB[27 * C_DIM * NJ];    // offset weights: [tap][c][j], j padded to 96
__device__ __align__(16) float g_W2t[27 * C_DIM * C_DIM]; // main weights: [tap][c][o]

// ============================================================
// Kernel A: transpose x (T,C,H,W) -> xt (T,H,W,C)
// ============================================================
__global__ void transpose_kernel(const float* __restrict__ x) {
    __shared__ float tile[32][33];
    int th = blockIdx.z;             // t*128 + h
    int t = th >> 7, h = th & 127;
    int c0 = blockIdx.y * 32;        // 0 or 32
    int w0 = blockIdx.x * 32;        // 0,32,64,96
    int tx = threadIdx.x, ty = threadIdx.y;
    // read coalesced along w
    tile[ty][tx] = x[(((size_t)t * C_DIM + (c0 + ty)) * H_DIM + h) * W_DIM + (w0 + tx)];
    __syncthreads();
    // write coalesced along c
    g_xt[(((size_t)th * W_DIM) + (w0 + ty)) * C_DIM + (c0 + tx)] = tile[tx][ty];
}

// ============================================================
// Kernel W: re-layout weights
//   offset_w (81,64,3,3,3) -> g_WtB[tap][c][j pad 96]
//   weight   (64,64,3,3,3) -> g_W2t[tap][c][o]
// ============================================================
__global__ void prep_weights(const float* __restrict__ ow, const float* __restrict__ wgt) {
    int i = blockIdx.x * blockDim.x + threadIdx.x;
    if (i < 27 * 64 * NJ) {
        int j   = i % NJ;
        int c   = (i / NJ) % 64;
        int tap = i / (NJ * 64);
        g_WtB[i] = (j < NJR) ? ow[((size_t)j * 64 + c) * 27 + tap] : 0.f;
    }
    if (i < 27 * 64 * 64) {
        int o   = i % 64;
        int c   = (i / 64) % 64;
        int tap = i / (64 * 64);
        g_W2t[i] = wgt[((size_t)o * 64 + c) * 27 + tap];
    }
}

// ============================================================
// Kernel B: offset conv (implicit GEMM)
//   block = one (t,h) row: 128 w positions x 96 j, K = 27 taps * 64 c
//   smem: xrow [130][65] (w'=-1..128, padded stride), ws [64][96]
// ============================================================
#define SMEM_B ((130 * 65 + 64 * NJ) * 4)

__global__ void __launch_bounds__(256) offset_conv_kernel(const float* __restrict__ offb) {
    extern __shared__ float sm[];
    float* xrow = sm;               // 130*65
    float* ws   = sm + 130 * 65;    // 64*96

    int th = blockIdx.x;
    int t = th >> 7, h = th & 127;
    int tid = threadIdx.x;
    int tj = tid & 15;     // j group: j0 = tj*6
    int tw = tid >> 4;     // w group: w0 = tw*8

    float acc[8][6];
#pragma unroll
    for (int i = 0; i < 8; i++)
#pragma unroll
        for (int j = 0; j < 6; j++) acc[i][j] = 0.f;

    for (int kt = 0; kt < 3; kt++) {
        int ts = t + kt - 1;
        if (ts < 0 || ts >= T_DIM) continue;          // uniform across block
        for (int kh = 0; kh < 3; kh++) {
            int hs = h + kh - 1;
            if (hs < 0 || hs >= H_DIM) continue;      // uniform across block
            __syncthreads();                          // xrow reuse barrier
            const float* src = g_xt + ((size_t)(ts * H_DIM + hs) * W_DIM) * C_DIM;
            for (int idx = tid; idx < 130 * 64; idx += 256) {
                int wp = idx >> 6, c = idx & 63;
                int wg = wp - 1;
                xrow[wp * 65 + c] = (wg >= 0 && wg < W_DIM) ? src[(size_t)wg * C_DIM + c] : 0.f;
            }
            for (int kw = 0; kw < 3; kw++) {
                int tap = kt * 9 + kh * 3 + kw;
                __syncthreads();                      // ws reuse + xrow ready
                const float* wsrc = g_WtB + (size_t)tap * (64 * NJ);
                for (int idx = tid; idx < 64 * NJ; idx += 256) ws[idx] = wsrc[idx];
                __syncthreads();

                const float* ab = xrow + (tw * 8 + kw) * 65;
#pragma unroll 4
                for (int c = 0; c < 64; c++) {
                    float a[8], b[6];
#pragma unroll
                    for (int i = 0; i < 8; i++) a[i] = ab[i * 65 + c];
#pragma unroll
                    for (int j = 0; j < 6; j++) b[j] = ws[c * NJ + tj * 6 + j];
#pragma unroll
                    for (int i = 0; i < 8; i++)
#pragma unroll
                        for (int j = 0; j < 6; j++)
                            acc[i][j] = fmaf(a[i], b[j], acc[i][j]);
                }
            }
        }
    }

    size_t rowbase = (size_t)th * W_DIM;
#pragma unroll
    for (int j = 0; j < 6; j++) {
        int jg = tj * 6 + j;
        if (jg >= NJR) continue;
        float bias = offb[jg];
#pragma unroll
        for (int i = 0; i < 8; i++) {
            int w = tw * 8 + i;
            g_off[(rowbase + w) * NJR + jg] = acc[i][j] + bias;
        }
    }
}

// ============================================================
// Kernel C: deformable sampling + weight contraction + residual
//   block = one (t,h) row: 128 w positions x 64 out channels
//   per tap: build sampled tile s[128][64] (trilinear, zero-fill OOB),
//   then GEMM-accumulate with 64x64 tap weight.
// ============================================================
#define SMEM_C ((128 * 68 + 64 * 64 + 3 * 128) * 4)

__global__ void __launch_bounds__(256) deform_kernel(const float* __restrict__ x,
                                                     const float* __restrict__ gamma,
                                                     float* __restrict__ out) {
    extern __shared__ float sm[];
    float* stile = sm;                      // [128][68]
    float* w2s   = sm + 128 * 68;           // [64][64]
    float* sdt   = w2s + 64 * 64;           // [128]
    float* sdh   = sdt + 128;
    float* sdw   = sdh + 128;

    int th = blockIdx.x;
    int t = th >> 7, h = th & 127;
    int tid = threadIdx.x;
    int to = tid & 15;      // o group: o0 = to*4
    int tw = tid >> 4;      // w group: w0 = tw*8

    int wsamp = tid >> 1;           // sampling: each thread = one w, half the channels
    int cf = (tid & 1) * 32;

    float acc[8][4];
#pragma unroll
    for (int i = 0; i < 8; i++)
#pragma unroll
        for (int j = 0; j < 4; j++) acc[i][j] = 0.f;

    size_t prow = (size_t)th * W_DIM;

    for (int k = 0; k < 27; k++) {
        int kt = k / 9, kh = (k / 3) % 3, kw = k % 3;
        __syncthreads();            // protect smem reuse from previous tap's GEMM
        if (tid < 128) {
            size_t pb = (prow + tid) * NJR;
            sdt[tid] = g_off[pb + k];
            sdh[tid] = g_off[pb + 27 + k];
            sdw[tid] = g_off[pb + 54 + k];
        }
        const float* wsrc = g_W2t + (size_t)k * 4096;
        for (int idx = tid; idx < 4096; idx += 256) w2s[idx] = wsrc[idx];
        __syncthreads();

        // ---- build sampled tile ----
        {
            float tc = (float)(t + kt - 1) + sdt[wsamp];
            float hc = (float)(h + kh - 1) + sdh[wsamp];
            float wc = (float)(wsamp + kw - 1) + sdw[wsamp];
            float t0f = floorf(tc), h0f = floorf(hc), w0f = floorf(wc);
            float lt = tc - t0f, lh = hc - h0f, lw = wc - w0f;
            int t0 = (int)t0f, h0 = (int)h0f, w0 = (int)w0f;
            float wts[2] = {1.f - lt, lt};
            float whs[2] = {1.f - lh, lh};
            float wws[2] = {1.f - lw, lw};

            const float* cp[8];
            float cw[8];
            int n = 0;
#pragma unroll
            for (int dt = 0; dt < 2; dt++)
#pragma unroll
                for (int dh = 0; dh < 2; dh++)
#pragma unroll
                    for (int dw = 0; dw < 2; dw++) {
                        int ti = t0 + dt, hi = h0 + dh, wi = w0 + dw;
                        bool valid = (unsigned)ti < T_DIM && (unsigned)hi < H_DIM &&
                                     (unsigned)wi < W_DIM;
                        cw[n] = valid ? wts[dt] * whs[dh] * wws[dw] : 0.f;
                        cp[n] = valid
                                    ? (g_xt + (((size_t)ti * H_DIM + hi) * W_DIM + wi) * C_DIM + cf)
                                    : (g_xt + cf);   // safe dummy, weight is 0
                        n++;
                    }

            float* sd = stile + wsamp * 68 + cf;
#pragma unroll
            for (int cc = 0; cc < 32; cc += 4) {
                float4 a = make_float4(0.f, 0.f, 0.f, 0.f);
#pragma unroll
                for (int q = 0; q < 8; q++) {
                    float4 v = *reinterpret_cast<const float4*>(cp[q] + cc);
                    a.x = fmaf(cw[q], v.x, a.x);
                    a.y = fmaf(cw[q], v.y, a.y);
                    a.z = fmaf(cw[q], v.z, a.z);
                    a.w = fmaf(cw[q], v.w, a.w);
                }
                *reinterpret_cast<float4*>(sd + cc) = a;
            }
        }
        __syncthreads();

        // ---- GEMM accumulate: acc[w][o] += s[w][c] * w2s[c][o] ----
        const float* ab = stile + tw * 8 * 68;
#pragma unroll 4
        for (int c = 0; c < 64; c++) {
            float4 b = *reinterpret_cast<const float4*>(w2s + c * 64 + to * 4);
            float a[8];
#pragma unroll
            for (int i = 0; i < 8; i++) a[i] = ab[i * 68 + c];
#pragma unroll
            for (int i = 0; i < 8; i++) {
                acc[i][0] = fmaf(a[i], b.x, acc[i][0]);
                acc[i][1] = fmaf(a[i], b.y, acc[i][1]);
                acc[i][2] = fmaf(a[i], b.z, acc[i][2]);
                acc[i][3] = fmaf(a[i], b.w, acc[i][3]);
            }
        }
    }

    // ---- epilogue: out = gamma * conv + x  (layout T,C,H,W) ----
    float g = gamma[0];
#pragma unroll
    for (int jo = 0; jo < 4; jo++) {
        int o = to * 4 + jo;
        size_t ob = (((size_t)t * C_DIM + o) * H_DIM + h) * W_DIM;
#pragma unroll
        for (int i = 0; i < 8; i++) {
            int w = tw * 8 + i;
            out[ob + w] = fmaf(g, acc[i][jo], x[ob + w]);
        }
    }
}

// ============================================================
// launch
// ============================================================
extern "C" void kernel_launch(void* const* d_in, const int* in_sizes, int n_in,
                              void* d_out, int out_size) {
    const float* x     = (const float*)d_in[0];
    const float* ow    = (const float*)d_in[1];
    const float* ob    = (const float*)d_in[2];
    const float* wgt   = (const float*)d_in[3];
    const float* gamma = (const float*)d_in[4];
    float* out = (float*)d_out;

    // Idempotent; first (non-captured) correctness call makes these stick.
    cudaFuncSetAttribute(offset_conv_kernel,
                         cudaFuncAttributeMaxDynamicSharedMemorySize, SMEM_B);
    cudaFuncSetAttribute(deform_kernel,
                         cudaFuncAttributeMaxDynamicSharedMemorySize, SMEM_C);

    dim3 tb(32, 32);
    dim3 tg(4, 2, T_DIM * H_DIM);
    transpose_kernel<<<tg, tb>>>(x);

    prep_weights<<<(27 * 64 * NJ + 255) / 256, 256>>>(ow, wgt);

    offset_conv_kernel<<<T_DIM * H_DIM, 256, SMEM_B>>>(ob);

    deform_kernel<<<T_DIM * H_DIM, 256, SMEM_C>>>(x, gamma, out);
}

// round 9
// speedup vs baseline: 1.0009x; 1.0008x over previous
#include <cuda_runtime.h>
#include <math.h>

// Problem constants
#define T_DIM 4
#define C_DIM 64
#define H_DIM 128
#define W_DIM 128
#define HW    (H_DIM * W_DIM)        // 16384
#define NPOS  (T_DIM * HW)           // 65536
#define NJ    96                     // padded offset-conv output channels
#define NJR   81                     // real offset channels (3*27)

// -------- device scratch (no allocations allowed) --------
__device__ __align__(16) float g_xt[NPOS * C_DIM];        // x channels-last: [t][h][w][c]
__device__ __align__(16) float g_off[NPOS * NJR];         // offsets: [pos][81]
__device__ __align__(16) float g_WtB[27 * C_DIM * NJ];    // offset weights: [tap][c][j], j padded to 96
__device__ __align__(16) float g_W2t[27 * C_DIM * C_DIM]; // main weights: [tap][c][o]

// ============================================================
// Kernel A: transpose x (T,C,H,W) -> xt (T,H,W,C)
// ============================================================
__global__ void transpose_kernel(const float* __restrict__ x) {
    __shared__ float tile[32][33];
    int th = blockIdx.z;             // t*128 + h
    int t = th >> 7, h = th & 127;
    int c0 = blockIdx.y * 32;        // 0 or 32
    int w0 = blockIdx.x * 32;        // 0,32,64,96
    int tx = threadIdx.x, ty = threadIdx.y;
    // read coalesced along w
    tile[ty][tx] = x[(((size_t)t * C_DIM + (c0 + ty)) * H_DIM + h) * W_DIM + (w0 + tx)];
    __syncthreads();
    // write coalesced along c
    g_xt[(((size_t)th * W_DIM) + (w0 + ty)) * C_DIM + (c0 + tx)] = tile[tx][ty];
}

// ============================================================
// Kernel W: re-layout weights
//   offset_w (81,64,3,3,3) -> g_WtB[tap][c][j pad 96]
//   weight   (64,64,3,3,3) -> g_W2t[tap][c][o]
// ============================================================
__global__ void prep_weights(const float* __restrict__ ow, const float* __restrict__ wgt) {
    int i = blockIdx.x * blockDim.x + threadIdx.x;
    if (i < 27 * 64 * NJ) {
        int j   = i % NJ;
        int c   = (i / NJ) % 64;
        int tap = i / (NJ * 64);
        g_WtB[i] = (j < NJR) ? ow[((size_t)j * 64 + c) * 27 + tap] : 0.f;
    }
    if (i < 27 * 64 * 64) {
        int o   = i % 64;
        int c   = (i / 64) % 64;
        int tap = i / (64 * 64);
        g_W2t[i] = wgt[((size_t)o * 64 + c) * 27 + tap];
    }
}

// ============================================================
// Kernel B: offset conv (implicit GEMM)
//   block = one (t,h) row: 128 w positions x 96 j, K = 27 taps * 64 c
//   smem: xrow [130][65] (w'=-1..128, padded stride), ws [64][96]
// ============================================================
#define SMEM_B ((130 * 65 + 64 * NJ) * 4)

__global__ void __launch_bounds__(256) offset_conv_kernel(const float* __restrict__ offb) {
    extern __shared__ float sm[];
    float* xrow = sm;               // 130*65
    float* ws   = sm + 130 * 65;    // 64*96

    int th = blockIdx.x;
    int t = th >> 7, h = th & 127;
    int tid = threadIdx.x;
    int tj = tid & 15;     // j group: j0 = tj*6
    int tw = tid >> 4;     // w group: w0 = tw*8

    float acc[8][6];
#pragma unroll
    for (int i = 0; i < 8; i++)
#pragma unroll
        for (int j = 0; j < 6; j++) acc[i][j] = 0.f;

    for (int kt = 0; kt < 3; kt++) {
        int ts = t + kt - 1;
        if (ts < 0 || ts >= T_DIM) continue;          // uniform across block
        for (int kh = 0; kh < 3; kh++) {
            int hs = h + kh - 1;
            if (hs < 0 || hs >= H_DIM) continue;      // uniform across block
            __syncthreads();                          // xrow reuse barrier
            const float* src = g_xt + ((size_t)(ts * H_DIM + hs) * W_DIM) * C_DIM;
            for (int idx = tid; idx < 130 * 64; idx += 256) {
                int wp = idx >> 6, c = idx & 63;
                int wg = wp - 1;
                xrow[wp * 65 + c] = (wg >= 0 && wg < W_DIM) ? src[(size_t)wg * C_DIM + c] : 0.f;
            }
            for (int kw = 0; kw < 3; kw++) {
                int tap = kt * 9 + kh * 3 + kw;
                __syncthreads();                      // ws reuse + xrow ready
                const float* wsrc = g_WtB + (size_t)tap * (64 * NJ);
                for (int idx = tid; idx < 64 * NJ; idx += 256) ws[idx] = wsrc[idx];
                __syncthreads();

                const float* ab = xrow + (tw * 8 + kw) * 65;
#pragma unroll 4
                for (int c = 0; c < 64; c++) {
                    float a[8], b[6];
#pragma unroll
                    for (int i = 0; i < 8; i++) a[i] = ab[i * 65 + c];
#pragma unroll
                    for (int j = 0; j < 6; j++) b[j] = ws[c * NJ + tj * 6 + j];
#pragma unroll
                    for (int i = 0; i < 8; i++)
#pragma unroll
                        for (int j = 0; j < 6; j++)
                            acc[i][j] = fmaf(a[i], b[j], acc[i][j]);
                }
            }
        }
    }

    size_t rowbase = (size_t)th * W_DIM;
#pragma unroll
    for (int j = 0; j < 6; j++) {
        int jg = tj * 6 + j;
        if (jg >= NJR) continue;
        float bias = offb[jg];
#pragma unroll
        for (int i = 0; i < 8; i++) {
            int w = tw * 8 + i;
            g_off[(rowbase + w) * NJR + jg] = acc[i][j] + bias;
        }
    }
}

// ============================================================
// Kernel C: deformable sampling + weight contraction + residual
//   block = one (t,h) row: 128 w positions x 64 out channels
//   per tap: build sampled tile s[128][64] (trilinear, zero-fill OOB),
//   then GEMM-accumulate with 64x64 tap weight.
// ============================================================
#define SMEM_C ((128 * 68 + 64 * 64 + 3 * 128) * 4)

__global__ void __launch_bounds__(256) deform_kernel(const float* __restrict__ x,
                                                     const float* __restrict__ gamma,
                                                     float* __restrict__ out) {
    extern __shared__ float sm[];
    float* stile = sm;                      // [128][68]
    float* w2s   = sm + 128 * 68;           // [64][64]
    float* sdt   = w2s + 64 * 64;           // [128]
    float* sdh   = sdt + 128;
    float* sdw   = sdh + 128;

    int th = blockIdx.x;
    int t = th >> 7, h = th & 127;
    int tid = threadIdx.x;
    int to = tid & 15;      // o group: o0 = to*4
    int tw = tid >> 4;      // w group: w0 = tw*8

    int wsamp = tid >> 1;           // sampling: each thread = one w, half the channels
    int cf = (tid & 1) * 32;

    float acc[8][4];
#pragma unroll
    for (int i = 0; i < 8; i++)
#pragma unroll
        for (int j = 0; j < 4; j++) acc[i][j] = 0.f;

    size_t prow = (size_t)th * W_DIM;

    for (int k = 0; k < 27; k++) {
        int kt = k / 9, kh = (k / 3) % 3, kw = k % 3;
        __syncthreads();            // protect smem reuse from previous tap's GEMM
        if (tid < 128) {
            size_t pb = (prow + tid) * NJR;
            sdt[tid] = g_off[pb + k];
            sdh[tid] = g_off[pb + 27 + k];
            sdw[tid] = g_off[pb + 54 + k];
        }
        const float* wsrc = g_W2t + (size_t)k * 4096;
        for (int idx = tid; idx < 4096; idx += 256) w2s[idx] = wsrc[idx];
        __syncthreads();

        // ---- build sampled tile ----
        {
            float tc = (float)(t + kt - 1) + sdt[wsamp];
            float hc = (float)(h + kh - 1) + sdh[wsamp];
            float wc = (float)(wsamp + kw - 1) + sdw[wsamp];
            float t0f = floorf(tc), h0f = floorf(hc), w0f = floorf(wc);
            float lt = tc - t0f, lh = hc - h0f, lw = wc - w0f;
            int t0 = (int)t0f, h0 = (int)h0f, w0 = (int)w0f;
            float wts[2] = {1.f - lt, lt};
            float whs[2] = {1.f - lh, lh};
            float wws[2] = {1.f - lw, lw};

            const float* cp[8];
            float cw[8];
            int n = 0;
#pragma unroll
            for (int dt = 0; dt < 2; dt++)
#pragma unroll
                for (int dh = 0; dh < 2; dh++)
#pragma unroll
                    for (int dw = 0; dw < 2; dw++) {
                        int ti = t0 + dt, hi = h0 + dh, wi = w0 + dw;
                        bool valid = (unsigned)ti < T_DIM && (unsigned)hi < H_DIM &&
                                     (unsigned)wi < W_DIM;
                        cw[n] = valid ? wts[dt] * whs[dh] * wws[dw] : 0.f;
                        cp[n] = valid
                                    ? (g_xt + (((size_t)ti * H_DIM + hi) * W_DIM + wi) * C_DIM + cf)
                                    : (g_xt + cf);   // safe dummy, weight is 0
                        n++;
                    }

            float* sd = stile + wsamp * 68 + cf;
#pragma unroll
            for (int cc = 0; cc < 32; cc += 4) {
                float4 a = make_float4(0.f, 0.f, 0.f, 0.f);
#pragma unroll
                for (int q = 0; q < 8; q++) {
                    float4 v = *reinterpret_cast<const float4*>(cp[q] + cc);
                    a.x = fmaf(cw[q], v.x, a.x);
                    a.y = fmaf(cw[q], v.y, a.y);
                    a.z = fmaf(cw[q], v.z, a.z);
                    a.w = fmaf(cw[q], v.w, a.w);
                }
                *reinterpret_cast<float4*>(sd + cc) = a;
            }
        }
        __syncthreads();

        // ---- GEMM accumulate: acc[w][o] += s[w][c] * w2s[c][o] ----
        const float* ab = stile + tw * 8 * 68;
#pragma unroll 4
        for (int c = 0; c < 64; c++) {
            float4 b = *reinterpret_cast<const float4*>(w2s + c * 64 + to * 4);
            float a[8];
#pragma unroll
            for (int i = 0; i < 8; i++) a[i] = ab[i * 68 + c];
#pragma unroll
            for (int i = 0; i < 8; i++) {
                acc[i][0] = fmaf(a[i], b.x, acc[i][0]);
                acc[i][1] = fmaf(a[i], b.y, acc[i][1]);
                acc[i][2] = fmaf(a[i], b.z, acc[i][2]);
                acc[i][3] = fmaf(a[i], b.w, acc[i][3]);
            }
        }
    }

    // ---- epilogue: out = gamma * conv + x  (layout T,C,H,W) ----
    float g = gamma[0];
#pragma unroll
    for (int jo = 0; jo < 4; jo++) {
        int o = to * 4 + jo;
        size_t ob = (((size_t)t * C_DIM + o) * H_DIM + h) * W_DIM;
#pragma unroll
        for (int i = 0; i < 8; i++) {
            int w = tw * 8 + i;
            out[ob + w] = fmaf(g, acc[i][jo], x[ob + w]);
        }
    }
}

// ============================================================
// launch
// ============================================================
extern "C" void kernel_launch(void* const* d_in, const int* in_sizes, int n_in,
                              void* d_out, int out_size) {
    const float* x     = (const float*)d_in[0];
    const float* ow    = (const float*)d_in[1];
    const float* ob    = (const float*)d_in[2];
    const float* wgt   = (const float*)d_in[3];
    const float* gamma = (const float*)d_in[4];
    float* out = (float*)d_out;

    // Idempotent; first (non-captured) correctness call makes these stick.
    cudaFuncSetAttribute(offset_conv_kernel,
                         cudaFuncAttributeMaxDynamicSharedMemorySize, SMEM_B);
    cudaFuncSetAttribute(deform_kernel,
                         cudaFuncAttributeMaxDynamicSharedMemorySize, SMEM_C);

    dim3 tb(32, 32);
    dim3 tg(4, 2, T_DIM * H_DIM);
    transpose_kernel<<<tg, tb>>>(x);

    prep_weights<<<(27 * 64 * NJ + 255) / 256, 256>>>(ow, wgt);

    offset_conv_kernel<<<T_DIM * H_DIM, 256, SMEM_B>>>(ob);

    deform_kernel<<<T_DIM * H_DIM, 256, SMEM_C>>>(x, gamma, out);
}

// round 10
// speedup vs baseline: 1.0026x; 1.0017x over previous
#include <cuda_runtime.h>
#include <math.h>

// Problem constants
#define T_DIM 4
#define C_DIM 64
#define H_DIM 128
#define W_DIM 128
#define HW    (H_DIM * W_DIM)        // 16384
#define NPOS  (T_DIM * HW)           // 65536
#define NJ    96                     // padded offset-conv output channels
#define NJR   81                     // real offset channels (3*27)

// -------- device scratch (no allocations allowed) --------
__device__ __align__(16) float g_xt[NPOS * C_DIM];        // x channels-last: [t][h][w][c]
__device__ __align__(16) float g_off[NPOS * NJR];         // offsets: [pos][81]
__device__ __align__(16) float g_WtB[27 * C_DIM * NJ];    // offset weights: [tap][c][j], j padded to 96
__device__ __align__(16) float g_W2t[27 * C_DIM * C_DIM]; // main weights: [tap][c][o]

// ============================================================
// Kernel A: transpose x (T,C,H,W) -> xt (T,H,W,C)
// ============================================================
__global__ void transpose_kernel(const float* __restrict__ x) {
    __shared__ float tile[32][33];
    int th = blockIdx.z;             // t*128 + h
    int t = th >> 7, h = th & 127;
    int c0 = blockIdx.y * 32;        // 0 or 32
    int w0 = blockIdx.x * 32;        // 0,32,64,96
    int tx = threadIdx.x, ty = threadIdx.y;
    // read coalesced along w
    tile[ty][tx] = x[(((size_t)t * C_DIM + (c0 + ty)) * H_DIM + h) * W_DIM + (w0 + tx)];
    __syncthreads();
    // write coalesced along c
    g_xt[(((size_t)th * W_DIM) + (w0 + ty)) * C_DIM + (c0 + tx)] = tile[tx][ty];
}

// ============================================================
// Kernel W: re-layout weights
//   offset_w (81,64,3,3,3) -> g_WtB[tap][c][j pad 96]
//   weight   (64,64,3,3,3) -> g_W2t[tap][c][o]
// ============================================================
__global__ void prep_weights(const float* __restrict__ ow, const float* __restrict__ wgt) {
    int i = blockIdx.x * blockDim.x + threadIdx.x;
    if (i < 27 * 64 * NJ) {
        int j   = i % NJ;
        int c   = (i / NJ) % 64;
        int tap = i / (NJ * 64);
        g_WtB[i] = (j < NJR) ? ow[((size_t)j * 64 + c) * 27 + tap] : 0.f;
    }
    if (i < 27 * 64 * 64) {
        int o   = i % 64;
        int c   = (i / 64) % 64;
        int tap = i / (64 * 64);
        g_W2t[i] = wgt[((size_t)o * 64 + c) * 27 + tap];
    }
}

// ============================================================
// Kernel B: offset conv (implicit GEMM)
//   block = one (t,h) row: 128 w positions x 96 j, K = 27 taps * 64 c
//   smem: xrow [130][65] (w'=-1..128, padded stride), ws [64][96]
// ============================================================
#define SMEM_B ((130 * 65 + 64 * NJ) * 4)

__global__ void __launch_bounds__(256) offset_conv_kernel(const float* __restrict__ offb) {
    extern __shared__ float sm[];
    float* xrow = sm;               // 130*65
    float* ws   = sm + 130 * 65;    // 64*96

    int th = blockIdx.x;
    int t = th >> 7, h = th & 127;
    int tid = threadIdx.x;
    int tj = tid & 15;     // j group: j0 = tj*6
    int tw = tid >> 4;     // w group: w0 = tw*8

    float acc[8][6];
#pragma unroll
    for (int i = 0; i < 8; i++)
#pragma unroll
        for (int j = 0; j < 6; j++) acc[i][j] = 0.f;

    for (int kt = 0; kt < 3; kt++) {
        int ts = t + kt - 1;
        if (ts < 0 || ts >= T_DIM) continue;          // uniform across block
        for (int kh = 0; kh < 3; kh++) {
            int hs = h + kh - 1;
            if (hs < 0 || hs >= H_DIM) continue;      // uniform across block
            __syncthreads();                          // xrow reuse barrier
            const float* src = g_xt + ((size_t)(ts * H_DIM + hs) * W_DIM) * C_DIM;
            for (int idx = tid; idx < 130 * 64; idx += 256) {
                int wp = idx >> 6, c = idx & 63;
                int wg = wp - 1;
                xrow[wp * 65 + c] = (wg >= 0 && wg < W_DIM) ? src[(size_t)wg * C_DIM + c] : 0.f;
            }
            for (int kw = 0; kw < 3; kw++) {
                int tap = kt * 9 + kh * 3 + kw;
                __syncthreads();                      // ws reuse + xrow ready
                const float* wsrc = g_WtB + (size_t)tap * (64 * NJ);
                for (int idx = tid; idx < 64 * NJ; idx += 256) ws[idx] = wsrc[idx];
                __syncthreads();

                const float* ab = xrow + (tw * 8 + kw) * 65;
#pragma unroll 4
                for (int c = 0; c < 64; c++) {
                    float a[8], b[6];
#pragma unroll
                    for (int i = 0; i < 8; i++) a[i] = ab[i * 65 + c];
#pragma unroll
                    for (int j = 0; j < 6; j++) b[j] = ws[c * NJ + tj * 6 + j];
#pragma unroll
                    for (int i = 0; i < 8; i++)
#pragma unroll
                        for (int j = 0; j < 6; j++)
                            acc[i][j] = fmaf(a[i], b[j], acc[i][j]);
                }
            }
        }
    }

    size_t rowbase = (size_t)th * W_DIM;
#pragma unroll
    for (int j = 0; j < 6; j++) {
        int jg = tj * 6 + j;
        if (jg >= NJR) continue;
        float bias = offb[jg];
#pragma unroll
        for (int i = 0; i < 8; i++) {
            int w = tw * 8 + i;
            g_off[(rowbase + w) * NJR + jg] = acc[i][j] + bias;
        }
    }
}

// ============================================================
// Kernel C: deformable sampling + weight contraction + residual
//   block = one (t,h) row: 128 w positions x 64 out channels
//   per tap: build sampled tile s[128][64] (trilinear, zero-fill OOB),
//   then GEMM-accumulate with 64x64 tap weight.
// ============================================================
#define SMEM_C ((128 * 68 + 64 * 64 + 3 * 128) * 4)

__global__ void __launch_bounds__(256) deform_kernel(const float* __restrict__ x,
                                                     const float* __restrict__ gamma,
                                                     float* __restrict__ out) {
    extern __shared__ float sm[];
    float* stile = sm;                      // [128][68]
    float* w2s   = sm + 128 * 68;           // [64][64]
    float* sdt   = w2s + 64 * 64;           // [128]
    float* sdh   = sdt + 128;
    float* sdw   = sdh + 128;

    int th = blockIdx.x;
    int t = th >> 7, h = th & 127;
    int tid = threadIdx.x;
    int to = tid & 15;      // o group: o0 = to*4
    int tw = tid >> 4;      // w group: w0 = tw*8

    int wsamp = tid >> 1;           // sampling: each thread = one w, half the channels
    int cf = (tid & 1) * 32;

    float acc[8][4];
#pragma unroll
    for (int i = 0; i < 8; i++)
#pragma unroll
        for (int j = 0; j < 4; j++) acc[i][j] = 0.f;

    size_t prow = (size_t)th * W_DIM;

    for (int k = 0; k < 27; k++) {
        int kt = k / 9, kh = (k / 3) % 3, kw = k % 3;
        __syncthreads();            // protect smem reuse from previous tap's GEMM
        if (tid < 128) {
            size_t pb = (prow + tid) * NJR;
            sdt[tid] = g_off[pb + k];
            sdh[tid] = g_off[pb + 27 + k];
            sdw[tid] = g_off[pb + 54 + k];
        }
        const float* wsrc = g_W2t + (size_t)k * 4096;
        for (int idx = tid; idx < 4096; idx += 256) w2s[idx] = wsrc[idx];
        __syncthreads();

        // ---- build sampled tile ----
        {
            float tc = (float)(t + kt - 1) + sdt[wsamp];
            float hc = (float)(h + kh - 1) + sdh[wsamp];
            float wc = (float)(wsamp + kw - 1) + sdw[wsamp];
            float t0f = floorf(tc), h0f = floorf(hc), w0f = floorf(wc);
            float lt = tc - t0f, lh = hc - h0f, lw = wc - w0f;
            int t0 = (int)t0f, h0 = (int)h0f, w0 = (int)w0f;
            float wts[2] = {1.f - lt, lt};
            float whs[2] = {1.f - lh, lh};
            float wws[2] = {1.f - lw, lw};

            const float* cp[8];
            float cw[8];
            int n = 0;
#pragma unroll
            for (int dt = 0; dt < 2; dt++)
#pragma unroll
                for (int dh = 0; dh < 2; dh++)
#pragma unroll
                    for (int dw = 0; dw < 2; dw++) {
                        int ti = t0 + dt, hi = h0 + dh, wi = w0 + dw;
                        bool valid = (unsigned)ti < T_DIM && (unsigned)hi < H_DIM &&
                                     (unsigned)wi < W_DIM;
                        cw[n] = valid ? wts[dt] * whs[dh] * wws[dw] : 0.f;
                        cp[n] = valid
                                    ? (g_xt + (((size_t)ti * H_DIM + hi) * W_DIM + wi) * C_DIM + cf)
                                    : (g_xt + cf);   // safe dummy, weight is 0
                        n++;
                    }

            float* sd = stile + wsamp * 68 + cf;
#pragma unroll
            for (int cc = 0; cc < 32; cc += 4) {
                float4 a = make_float4(0.f, 0.f, 0.f, 0.f);
#pragma unroll
                for (int q = 0; q < 8; q++) {
                    float4 v = *reinterpret_cast<const float4*>(cp[q] + cc);
                    a.x = fmaf(cw[q], v.x, a.x);
                    a.y = fmaf(cw[q], v.y, a.y);
                    a.z = fmaf(cw[q], v.z, a.z);
                    a.w = fmaf(cw[q], v.w, a.w);
                }
                *reinterpret_cast<float4*>(sd + cc) = a;
            }
        }
        __syncthreads();

        // ---- GEMM accumulate: acc[w][o] += s[w][c] * w2s[c][o] ----
        const float* ab = stile + tw * 8 * 68;
#pragma unroll 4
        for (int c = 0; c < 64; c++) {
            float4 b = *reinterpret_cast<const float4*>(w2s + c * 64 + to * 4);
            float a[8];
#pragma unroll
            for (int i = 0; i < 8; i++) a[i] = ab[i * 68 + c];
#pragma unroll
            for (int i = 0; i < 8; i++) {
                acc[i][0] = fmaf(a[i], b.x, acc[i][0]);
                acc[i][1] = fmaf(a[i], b.y, acc[i][1]);
                acc[i][2] = fmaf(a[i], b.z, acc[i][2]);
                acc[i][3] = fmaf(a[i], b.w, acc[i][3]);
            }
        }
    }

    // ---- epilogue: out = gamma * conv + x  (layout T,C,H,W) ----
    float g = gamma[0];
#pragma unroll
    for (int jo = 0; jo < 4; jo++) {
        int o = to * 4 + jo;
        size_t ob = (((size_t)t * C_DIM + o) * H_DIM + h) * W_DIM;
#pragma unroll
        for (int i = 0; i < 8; i++) {
            int w = tw * 8 + i;
            out[ob + w] = fmaf(g, acc[i][jo], x[ob + w]);
        }
    }
}

// ============================================================
// launch
// ============================================================
extern "C" void kernel_launch(void* const* d_in, const int* in_sizes, int n_in,
                              void* d_out, int out_size) {
    const float* x     = (const float*)d_in[0];
    const float* ow    = (const float*)d_in[1];
    const float* ob    = (const float*)d_in[2];
    const float* wgt   = (const float*)d_in[3];
    const float* gamma = (const float*)d_in[4];
    float* out = (float*)d_out;

    // Idempotent; first (non-captured) correctness call makes these stick.
    cudaFuncSetAttribute(offset_conv_kernel,
                         cudaFuncAttributeMaxDynamicSharedMemorySize, SMEM_B);
    cudaFuncSetAttribute(deform_kernel,
                         cudaFuncAttributeMaxDynamicSharedMemorySize, SMEM_C);

    dim3 tb(32, 32);
    dim3 tg(4, 2, T_DIM * H_DIM);
    transpose_kernel<<<tg, tb>>>(x);

    prep_weights<<<(27 * 64 * NJ + 255) / 256, 256>>>(ow, wgt);

    offset_conv_kernel<<<T_DIM * H_DIM, 256, SMEM_B>>>(ob);

    deform_kernel<<<T_DIM * H_DIM, 256, SMEM_C>>>(x, gamma, out);
}